// round 14
// baseline (speedup 1.0000x reference)
#include <cuda_runtime.h>
#include <cuda_bf16.h>
#include <cuda_fp16.h>
#include <cstdint>

#define N_NODES 50000
#define F 128
#define NOUT2 32
#define NE 800000

#define SCAN_BS 256
#define SCAN_NB ((N_NODES + SCAN_BS - 1) / SCAN_BS)   // 196
#define LBFLAG 0x80000000u
#define NB_BUILD 888                                  // 6 blocks/SM x 148 SMs

// ---------------- scratch (device globals: no allocation allowed) ----------
// INVARIANT: g_degi, g_lb, g_barg are all-zero on entry (zero-init at load;
// agg2 re-zeros them every call; barrier counters self-reset).
__device__ __align__(16) __half g_y1h[N_NODES * F];      // x @ W1 (fp16)
__device__ __align__(16) __half g_y2h[N_NODES * NOUT2];  // h1 @ W2 (fp16)
__device__ __align__(16) __nv_bfloat16 g_h1hi[N_NODES * F];
__device__ __align__(16) __nv_bfloat16 g_h1lo[N_NODES * F];
__device__ __align__(16) __nv_bfloat16 g_b1hi[F * F];     // W1^T [n][k]
__device__ __align__(16) __nv_bfloat16 g_b1lo[F * F];
__device__ __align__(16) __nv_bfloat16 g_b2hi[NOUT2 * F]; // W2^T [n][k]
__device__ __align__(16) __nv_bfloat16 g_b2lo[NOUT2 * F];
__device__ int g_csr[NE];
__device__ int g_rowptr[N_NODES + 1];
__device__ int g_cur[N_NODES];
__device__ int g_degi[N_NODES];
__device__ unsigned g_lb[SCAN_NB];
__device__ unsigned g_barc[2];
__device__ volatile unsigned g_barg[2];

// ---------------- helpers ---------------------------------------------------
__device__ __forceinline__ uint32_t smem_u32(const void* p) {
    uint32_t a;
    asm("{ .reg .u64 t; cvta.to.shared.u64 t, %1; cvt.u32.u64 %0, t; }"
        : "=r"(a) : "l"(p));
    return a;
}
#define LDSM4(r0, r1, r2, r3, a) \
    asm volatile("ldmatrix.sync.aligned.m8n8.x4.shared.b16 {%0,%1,%2,%3}, [%4];" \
                 : "=r"(r0), "=r"(r1), "=r"(r2), "=r"(r3) : "r"(a))
#define LDSM2(r0, r1, a) \
    asm volatile("ldmatrix.sync.aligned.m8n8.x2.shared.b16 {%0,%1}, [%2];" \
                 : "=r"(r0), "=r"(r1) : "r"(a))
#define MMA16816(c, a, b) \
    asm volatile("mma.sync.aligned.m16n8k16.row.col.f32.bf16.bf16.f32 " \
                 "{%0,%1,%2,%3}, {%4,%5,%6,%7}, {%8,%9}, {%0,%1,%2,%3};" \
                 : "+f"((c)[0]), "+f"((c)[1]), "+f"((c)[2]), "+f"((c)[3]) \
                 : "r"((a)[0]), "r"((a)[1]), "r"((a)[2]), "r"((a)[3]), \
                   "r"((b)[0]), "r"((b)[1]))

__device__ __forceinline__ void acc_h4(float4& a, uint2 u) {
    float2 f0 = __half22float2(*reinterpret_cast<__half2*>(&u.x));
    float2 f1 = __half22float2(*reinterpret_cast<__half2*>(&u.y));
    a.x += f0.x; a.y += f0.y; a.z += f1.x; a.w += f1.y;
}

__device__ __forceinline__ int block_detect_is64(const int* e32) {
    int is64 = 1;
    #pragma unroll
    for (int k = 0; k < 32; ++k)
        if (e32[2 * k + 1] != 0) { is64 = 0; break; }
    return is64;
}

// sense-free grid barrier: counter self-resets; gen flag reset by agg2.
__device__ __forceinline__ void gridbar(int id) {
    __syncthreads();
    if (threadIdx.x == 0) {
        __threadfence();
        unsigned a = atomicAdd(&g_barc[id], 1u);
        if (a == NB_BUILD - 1) {
            g_barc[id] = 0;
            __threadfence();
            g_barg[id] = 1u;
        } else {
            while (g_barg[id] == 0u) { __nanosleep(32); }
        }
        __threadfence();
    }
    __syncthreads();
}

// ---------------- persistent CSR builder: deg + scan + fill ----------------
__global__ __launch_bounds__(256, 8) void build_kernel(const void* __restrict__ edges) {
    __shared__ int s64;
    if (threadIdx.x == 0) s64 = block_detect_is64((const int*)edges);
    __syncthreads();

    const int nt = NB_BUILD * 256;
    const int gt = blockIdx.x * 256 + threadIdx.x;

    // ---- phase 1: degree histogram ----
    if (s64) {
        const long long* E = (const long long*)edges;
        for (int e = gt; e < NE; e += nt)
            atomicAdd(&g_degi[(int)E[NE + e]], 1);
    } else {
        const int* E = (const int*)edges;
        for (int e = gt; e < NE; e += nt)
            atomicAdd(&g_degi[E[NE + e]], 1);
    }
    gridbar(0);

    // ---- phase 2: exclusive scan (blocks 0..195, decoupled lookback) ----
    if (blockIdx.x < SCAN_NB) {
        __shared__ int wred[8];
        __shared__ int wscn[8];
        __shared__ int base_sh;
        int b = blockIdx.x, t = threadIdx.x;
        int lane = t & 31, warp = t >> 5;
        int i = b * SCAN_BS + t;
        int v = (i < N_NODES) ? g_degi[i] : 0;

        int s = v;
        #pragma unroll
        for (int off = 1; off < 32; off <<= 1) {
            int u = __shfl_up_sync(0xffffffffu, s, off);
            if (lane >= off) s += u;
        }
        if (lane == 31) wred[warp] = s;
        __syncthreads();
        if (t < 8) {
            int ws = wred[t];
            #pragma unroll
            for (int off = 1; off < 8; off <<= 1) {
                int u = __shfl_up_sync(0xffu, ws, off);
                if ((int)t >= off) ws += u;
            }
            wscn[t] = ws;
            if (t == 7) atomicExch(&g_lb[b], LBFLAG | (unsigned)ws);
        }
        __syncthreads();

        int contrib = 0;
        if (t < b) {
            unsigned f;
            do { f = atomicAdd(&g_lb[t], 0u); } while (!(f & LBFLAG));
            contrib = (int)(f & ~LBFLAG);
        }
        #pragma unroll
        for (int off = 16; off > 0; off >>= 1)
            contrib += __shfl_down_sync(0xffffffffu, contrib, off);
        if (lane == 0) wred[warp] = contrib;
        __syncthreads();
        if (t == 0) {
            int base = 0;
            #pragma unroll
            for (int k = 0; k < 8; ++k) base += wred[k];
            base_sh = base;
            if (b == 0) g_rowptr[N_NODES] = NE;
        }
        __syncthreads();

        int excl = base_sh + (warp > 0 ? wscn[warp - 1] : 0) + (s - v);
        if (i < N_NODES) { g_rowptr[i] = excl; g_cur[i] = excl; }
    }
    gridbar(1);

    // ---- phase 3: CSR fill ----
    if (s64) {
        const long long* E = (const long long*)edges;
        for (int e = gt; e < NE; e += nt) {
            int s = (int)E[e];
            int d = (int)E[NE + e];
            int pos = atomicAdd(&g_cur[d], 1);
            g_csr[pos] = s;
        }
    } else {
        const int* E = (const int*)edges;
        for (int e = gt; e < NE; e += nt) {
            int s = E[e];
            int d = E[NE + e];
            int pos = atomicAdd(&g_cur[d], 1);
            g_csr[pos] = s;
        }
    }
}

// ---------------- W hi/lo split (side stream) ------------------------------
__global__ void wsplit_kernel(const float* __restrict__ W1,
                              const float* __restrict__ W2) {
    int i = blockIdx.x * blockDim.x + threadIdx.x;
    if (i < F * F) {
        int k = i >> 7, n = i & 127;
        float v = W1[i];
        __nv_bfloat16 h = __float2bfloat16(v);
        g_b1hi[n * F + k] = h;
        g_b1lo[n * F + k] = __float2bfloat16(v - __bfloat162float(h));
    } else if (i < F * F + F * NOUT2) {
        int q = i - F * F;
        int k = q >> 5, n = q & 31;
        float v = W2[q];
        __nv_bfloat16 h = __float2bfloat16(v);
        g_b2hi[n * F + k] = h;
        g_b2lo[n * F + k] = __float2bfloat16(v - __bfloat162float(h));
    }
}

// ---------------- mma.sync GEMM: Yh = A @ B^T (fp16 out) -------------------
template<int NCOLS, int LAYER>
__global__ __launch_bounds__(256) void gemm_mma_kernel(const float* __restrict__ x) {
    constexpr int ROWS = 64;
    constexpr int SROW = 136;
    constexpr int A_BYTES = ROWS * SROW * 2;
    constexpr int B_BYTES = NCOLS * SROW * 2;
    constexpr int OF_AHI = 0;
    constexpr int OF_ALO = A_BYTES;
    constexpr int OF_BHI = 2 * A_BYTES;
    constexpr int OF_BLO = OF_BHI + B_BYTES;
    constexpr int N8  = NCOLS / 32;
    constexpr int WNT = NCOLS / 4;
    constexpr int CS  = NCOLS + 4;

    const __nv_bfloat16* Bhi = (LAYER == 1) ? g_b1hi : g_b2hi;
    const __nv_bfloat16* Blo = (LAYER == 1) ? g_b1lo : g_b2lo;
    __half* Yh = (LAYER == 1) ? g_y1h : g_y2h;

    extern __shared__ char smem[];
    float* Csm = (float*)smem;
    uint32_t sb = smem_u32(smem);

    int t = threadIdx.x, lane = t & 31, wid = t >> 5;
    int row0 = blockIdx.x * ROWS;

    if constexpr (LAYER == 1) {
        for (int i = t; i < ROWS * 32; i += 256) {
            int r = i >> 5, c4 = i & 31;
            int gr = row0 + r;
            float4 v = make_float4(0.f, 0.f, 0.f, 0.f);
            if (gr < N_NODES) v = ((const float4*)(x + (size_t)gr * F))[c4];
            __nv_bfloat162 h0 = __floats2bfloat162_rn(v.x, v.y);
            __nv_bfloat162 h1 = __floats2bfloat162_rn(v.z, v.w);
            __nv_bfloat162 l0 = __floats2bfloat162_rn(v.x - __low2float(h0),
                                                      v.y - __high2float(h0));
            __nv_bfloat162 l1 = __floats2bfloat162_rn(v.z - __low2float(h1),
                                                      v.w - __high2float(h1));
            uint2 uh, ul;
            uh.x = *reinterpret_cast<uint32_t*>(&h0);
            uh.y = *reinterpret_cast<uint32_t*>(&h1);
            ul.x = *reinterpret_cast<uint32_t*>(&l0);
            ul.y = *reinterpret_cast<uint32_t*>(&l1);
            *(uint2*)(smem + OF_AHI + r * (SROW * 2) + c4 * 8) = uh;
            *(uint2*)(smem + OF_ALO + r * (SROW * 2) + c4 * 8) = ul;
        }
    } else {
        for (int i = t; i < ROWS * 16; i += 256) {
            int r = i >> 4, c = (i & 15) * 8;
            int gr = row0 + r;
            uint4 vh = make_uint4(0, 0, 0, 0), vl = make_uint4(0, 0, 0, 0);
            if (gr < N_NODES) {
                vh = *(const uint4*)(g_h1hi + (size_t)gr * F + c);
                vl = *(const uint4*)(g_h1lo + (size_t)gr * F + c);
            }
            *(uint4*)(smem + OF_AHI + r * (SROW * 2) + c * 2) = vh;
            *(uint4*)(smem + OF_ALO + r * (SROW * 2) + c * 2) = vl;
        }
    }
    for (int i = t; i < NCOLS * 16; i += 256) {
        int r = i >> 4, c = (i & 15) * 8;
        *(uint4*)(smem + OF_BHI + r * (SROW * 2) + c * 2) =
            *(const uint4*)(Bhi + (size_t)r * F + c);
        *(uint4*)(smem + OF_BLO + r * (SROW * 2) + c * 2) =
            *(const uint4*)(Blo + (size_t)r * F + c);
    }
    __syncthreads();

    int wm = wid & 1, wn = wid >> 1;
    int m0 = wm * 32, n0 = wn * WNT;

    float acc[2][N8][4];
    #pragma unroll
    for (int mi = 0; mi < 2; ++mi)
        #pragma unroll
        for (int nj = 0; nj < N8; ++nj)
            #pragma unroll
            for (int q = 0; q < 4; ++q) acc[mi][nj][q] = 0.f;

    int lrow = lane & 7, lsub = lane >> 3;
    int aRow = lrow + (lsub & 1) * 8, aCol = (lsub >> 1) * 8;
    int bRow = lrow + (lsub >> 1) * 8, bCol = (lsub & 1) * 8;
    int l16 = lane & 15;
    int b2Row = l16 & 7, b2Col = (l16 >> 3) * 8;

    const int passA[3] = { OF_AHI, OF_AHI, OF_ALO };
    const int passB[3] = { OF_BHI, OF_BLO, OF_BHI };

    #pragma unroll
    for (int p = 0; p < 3; ++p) {
        uint32_t Ab = sb + passA[p], Bb = sb + passB[p];
        #pragma unroll
        for (int k = 0; k < 8; ++k) {
            int k0 = k * 16;
            uint32_t a[2][4];
            #pragma unroll
            for (int mi = 0; mi < 2; ++mi) {
                uint32_t ad = Ab + ((m0 + mi * 16 + aRow) * SROW + k0 + aCol) * 2;
                LDSM4(a[mi][0], a[mi][1], a[mi][2], a[mi][3], ad);
            }
            uint32_t b[N8][2];
            if constexpr (N8 == 1) {
                uint32_t bd = Bb + ((n0 + b2Row) * SROW + k0 + b2Col) * 2;
                LDSM2(b[0][0], b[0][1], bd);
            } else {
                #pragma unroll
                for (int nj2 = 0; nj2 < N8 / 2; ++nj2) {
                    uint32_t bd = Bb + ((n0 + nj2 * 16 + bRow) * SROW + k0 + bCol) * 2;
                    uint32_t r0, r1, r2, r3;
                    LDSM4(r0, r1, r2, r3, bd);
                    b[nj2 * 2][0] = r0; b[nj2 * 2][1] = r1;
                    b[nj2 * 2 + 1][0] = r2; b[nj2 * 2 + 1][1] = r3;
                }
            }
            #pragma unroll
            for (int mi = 0; mi < 2; ++mi)
                #pragma unroll
                for (int nj = 0; nj < N8; ++nj)
                    MMA16816(acc[mi][nj], a[mi], b[nj]);
        }
    }

    __syncthreads();

    int g = lane >> 2, tp = lane & 3;
    #pragma unroll
    for (int mi = 0; mi < 2; ++mi)
        #pragma unroll
        for (int nj = 0; nj < N8; ++nj) {
            int rr = m0 + mi * 16 + g;
            int cc = n0 + nj * 8 + tp * 2;
            Csm[rr * CS + cc]           = acc[mi][nj][0];
            Csm[rr * CS + cc + 1]       = acc[mi][nj][1];
            Csm[(rr + 8) * CS + cc]     = acc[mi][nj][2];
            Csm[(rr + 8) * CS + cc + 1] = acc[mi][nj][3];
        }
    __syncthreads();

    for (int i = t; i < ROWS * (NCOLS / 8); i += 256) {
        int r = i / (NCOLS / 8), c8 = (i % (NCOLS / 8)) * 8;
        int row = row0 + r;
        if (row < N_NODES) {
            float4 u = *(float4*)&Csm[r * CS + c8];
            float4 w = *(float4*)&Csm[r * CS + c8 + 4];
            __half2 p0 = __floats2half2_rn(u.x, u.y);
            __half2 p1 = __floats2half2_rn(u.z, u.w);
            __half2 p2 = __floats2half2_rn(w.x, w.y);
            __half2 p3 = __floats2half2_rn(w.z, w.w);
            uint4 o;
            o.x = *reinterpret_cast<uint32_t*>(&p0);
            o.y = *reinterpret_cast<uint32_t*>(&p1);
            o.z = *reinterpret_cast<uint32_t*>(&p2);
            o.w = *reinterpret_cast<uint32_t*>(&p3);
            *(uint4*)(Yh + (size_t)row * NCOLS + c8) = o;
        }
    }
}

// ---------------- agg1: h1 = leaky((sum_nbr y1 + y1)*rinv + b1) -> bf16 ----
__global__ void agg1_kernel(const float* __restrict__ b1g) {
    int w = (blockIdx.x * blockDim.x + threadIdx.x) >> 5;
    if (w >= N_NODES) return;
    int lane = threadIdx.x & 31;
    const uint2* Y = (const uint2*)g_y1h;

    float4 a0 = make_float4(0.f, 0.f, 0.f, 0.f);
    float4 a1 = a0, a2 = a0, a3 = a0;
    acc_h4(a0, Y[(size_t)w * 32 + lane]);   // self

    int beg = g_rowptr[w], end = g_rowptr[w + 1];
    int j = beg;
    for (; j + 4 <= end; j += 4) {
        int s0 = g_csr[j], s1 = g_csr[j + 1], s2 = g_csr[j + 2], s3 = g_csr[j + 3];
        acc_h4(a0, Y[(size_t)s0 * 32 + lane]);
        acc_h4(a1, Y[(size_t)s1 * 32 + lane]);
        acc_h4(a2, Y[(size_t)s2 * 32 + lane]);
        acc_h4(a3, Y[(size_t)s3 * 32 + lane]);
    }
    for (; j < end; ++j)
        acc_h4(a0, Y[(size_t)g_csr[j] * 32 + lane]);

    float rinv = 1.0f / (float)(end - beg + 1);
    float4 b = ((const float4*)b1g)[lane];
    float4 h;
    h.x = (a0.x + a1.x + a2.x + a3.x) * rinv + b.x;
    h.y = (a0.y + a1.y + a2.y + a3.y) * rinv + b.y;
    h.z = (a0.z + a1.z + a2.z + a3.z) * rinv + b.z;
    h.w = (a0.w + a1.w + a2.w + a3.w) * rinv + b.w;
    h.x = h.x >= 0.f ? h.x : 0.01f * h.x;
    h.y = h.y >= 0.f ? h.y : 0.01f * h.y;
    h.z = h.z >= 0.f ? h.z : 0.01f * h.z;
    h.w = h.w >= 0.f ? h.w : 0.01f * h.w;

    __nv_bfloat162 p0 = __floats2bfloat162_rn(h.x, h.y);
    __nv_bfloat162 p1 = __floats2bfloat162_rn(h.z, h.w);
    __nv_bfloat162 q0 = __floats2bfloat162_rn(h.x - __low2float(p0), h.y - __high2float(p0));
    __nv_bfloat162 q1 = __floats2bfloat162_rn(h.z - __low2float(p1), h.w - __high2float(p1));
    ((__nv_bfloat162*)g_h1hi)[(size_t)w * 64 + lane * 2]     = p0;
    ((__nv_bfloat162*)g_h1hi)[(size_t)w * 64 + lane * 2 + 1] = p1;
    ((__nv_bfloat162*)g_h1lo)[(size_t)w * 64 + lane * 2]     = q0;
    ((__nv_bfloat162*)g_h1lo)[(size_t)w * 64 + lane * 2 + 1] = q1;
}

// ---------------- agg2: out = (sum_nbr y2 + y2)*rinv + b2; reset scratch ---
__global__ void agg2_kernel(const float* __restrict__ b2g,
                            float* __restrict__ out) {
    int gi = blockIdx.x * blockDim.x + threadIdx.x;
    // restore the zero-invariant for the next call/replay
    if (gi < N_NODES) g_degi[gi] = 0;
    if (gi < SCAN_NB) g_lb[gi] = 0u;
    if (gi < 2) g_barg[gi] = 0u;

    int gw = gi >> 5;
    int lane = threadIdx.x & 31;
    int node = gw * 4 + (lane >> 3);
    if (node >= N_NODES) return;
    int l8 = lane & 7;
    const uint2* Y = (const uint2*)g_y2h;

    float4 a0 = make_float4(0.f, 0.f, 0.f, 0.f);
    float4 a1 = a0, a2 = a0, a3 = a0;
    acc_h4(a0, Y[(size_t)node * 8 + l8]);   // self

    int beg = g_rowptr[node], end = g_rowptr[node + 1];
    int j = beg;
    for (; j + 4 <= end; j += 4) {
        int s0 = g_csr[j], s1 = g_csr[j + 1], s2 = g_csr[j + 2], s3 = g_csr[j + 3];
        acc_h4(a0, Y[(size_t)s0 * 8 + l8]);
        acc_h4(a1, Y[(size_t)s1 * 8 + l8]);
        acc_h4(a2, Y[(size_t)s2 * 8 + l8]);
        acc_h4(a3, Y[(size_t)s3 * 8 + l8]);
    }
    for (; j < end; ++j)
        acc_h4(a0, Y[(size_t)g_csr[j] * 8 + l8]);

    float rinv = 1.0f / (float)(end - beg + 1);
    float4 b = ((const float4*)b2g)[l8];
    float4 o;
    o.x = (a0.x + a1.x + a2.x + a3.x) * rinv + b.x;
    o.y = (a0.y + a1.y + a2.y + a3.y) * rinv + b.y;
    o.z = (a0.z + a1.z + a2.z + a3.z) * rinv + b.z;
    o.w = (a0.w + a1.w + a2.w + a3.w) * rinv + b.w;
    ((float4*)(out + (size_t)node * NOUT2))[l8] = o;
}

// ---------------- launch ----------------------------------------------------
extern "C" void kernel_launch(void* const* d_in, const int* in_sizes, int n_in,
                              void* d_out, int out_size) {
    const float* in_feat = (const float*)d_in[0];
    const void*  edges   = d_in[1];
    const float* W1      = (const float*)d_in[2];
    const float* b1      = (const float*)d_in[3];
    const float* W2      = (const float*)d_in[4];
    const float* b2      = (const float*)d_in[5];
    float* out = (float*)d_out;

    const int smem_g1 = 2 * (64 * 136 * 2) + 2 * (128 * 136 * 2);   // 104,448
    const int smem_g2 = 2 * (64 * 136 * 2) + 2 * (32 * 136 * 2);    //  52,224
    cudaFuncSetAttribute(gemm_mma_kernel<128, 1>,
                         cudaFuncAttributeMaxDynamicSharedMemorySize, smem_g1);
    cudaFuncSetAttribute(gemm_mma_kernel<32, 2>,
                         cudaFuncAttributeMaxDynamicSharedMemorySize, smem_g2);

    cudaStream_t s2;
    cudaEvent_t evFork, evJoin;
    cudaStreamCreateWithFlags(&s2, cudaStreamNonBlocking);
    cudaEventCreateWithFlags(&evFork, cudaEventDisableTiming);
    cudaEventCreateWithFlags(&evJoin, cudaEventDisableTiming);

    const int GB = (N_NODES + 63) / 64;   // 782

    // fork: side chain (W split -> GEMM1) depends on nothing else
    cudaEventRecord(evFork, 0);
    cudaStreamWaitEvent(s2, evFork, 0);
    wsplit_kernel<<<(F * F + F * NOUT2 + 255) / 256, 256, 0, s2>>>(W1, W2);
    gemm_mma_kernel<128, 1><<<GB, 256, smem_g1, s2>>>(in_feat);
    cudaEventRecord(evJoin, s2);

    // main chain: persistent one-kernel CSR build (deg + scan + fill)
    build_kernel<<<NB_BUILD, 256>>>(edges);

    // join: agg1 needs CSR (main) + y1h (side)
    cudaStreamWaitEvent(0, evJoin, 0);
    agg1_kernel<<<(N_NODES * 32 + 255) / 256, 256>>>(b1);
    gemm_mma_kernel<32, 2><<<GB, 256, smem_g2>>>(nullptr);
    agg2_kernel<<<((N_NODES + 3) / 4 * 32 + 255) / 256, 256>>>(b2, out);
}

// round 15
// speedup vs baseline: 1.1081x; 1.1081x over previous
#include <cuda_runtime.h>
#include <cuda_bf16.h>
#include <cuda_fp16.h>
#include <cstdint>

#define N_NODES 50000
#define F 128
#define NOUT2 32
#define NE 800000

#define SCAN_BS 256
#define SCAN_NB ((N_NODES + SCAN_BS - 1) / SCAN_BS)   // 196
#define LBFLAG 0x80000000u

// ---------------- scratch (device globals: no allocation allowed) ----------
__device__ __align__(16) __half g_y1h[N_NODES * F];      // x @ W1 (fp16)
__device__ __align__(16) __half g_y2h[N_NODES * NOUT2];  // h1 @ W2 (fp16)
__device__ __align__(16) __nv_bfloat16 g_h1hi[N_NODES * F];
__device__ __align__(16) __nv_bfloat16 g_h1lo[N_NODES * F];
__device__ __align__(16) __nv_bfloat16 g_b1hi[F * F];     // W1^T [n][k]
__device__ __align__(16) __nv_bfloat16 g_b1lo[F * F];
__device__ __align__(16) __nv_bfloat16 g_b2hi[NOUT2 * F]; // W2^T [n][k]
__device__ __align__(16) __nv_bfloat16 g_b2lo[NOUT2 * F];
__device__ __align__(16) int g_csr[NE];
__device__ int g_rowptr[N_NODES + 1];
__device__ int g_cur[N_NODES];
__device__ int g_degi[N_NODES];
__device__ unsigned g_lb[SCAN_NB];
__device__ int g_is64;

// ---------------- helpers ---------------------------------------------------
__device__ __forceinline__ uint32_t smem_u32(const void* p) {
    uint32_t a;
    asm("{ .reg .u64 t; cvta.to.shared.u64 t, %1; cvt.u32.u64 %0, t; }"
        : "=r"(a) : "l"(p));
    return a;
}
#define LDSM4(r0, r1, r2, r3, a) \
    asm volatile("ldmatrix.sync.aligned.m8n8.x4.shared.b16 {%0,%1,%2,%3}, [%4];" \
                 : "=r"(r0), "=r"(r1), "=r"(r2), "=r"(r3) : "r"(a))
#define LDSM2(r0, r1, a) \
    asm volatile("ldmatrix.sync.aligned.m8n8.x2.shared.b16 {%0,%1}, [%2];" \
                 : "=r"(r0), "=r"(r1) : "r"(a))
#define MMA16816(c, a, b) \
    asm volatile("mma.sync.aligned.m16n8k16.row.col.f32.bf16.bf16.f32 " \
                 "{%0,%1,%2,%3}, {%4,%5,%6,%7}, {%8,%9}, {%0,%1,%2,%3};" \
                 : "+f"((c)[0]), "+f"((c)[1]), "+f"((c)[2]), "+f"((c)[3]) \
                 : "r"((a)[0]), "r"((a)[1]), "r"((a)[2]), "r"((a)[3]), \
                   "r"((b)[0]), "r"((b)[1]))

__device__ __forceinline__ void acc_h4(float4& a, uint2 u) {
    float2 f0 = __half22float2(*reinterpret_cast<__half2*>(&u.x));
    float2 f1 = __half22float2(*reinterpret_cast<__half2*>(&u.y));
    a.x += f0.x; a.y += f0.y; a.z += f1.x; a.w += f1.y;
}

// ---------------- init: zero deg + lb flags + dtype detect + W split -------
__global__ void init_kernel(const int* e32,
                            const float* __restrict__ W1,
                            const float* __restrict__ W2) {
    int i = blockIdx.x * blockDim.x + threadIdx.x;
    if (i < N_NODES) g_degi[i] = 0;
    if (i < SCAN_NB) g_lb[i] = 0u;
    if (i < F * F) {
        int k = i >> 7, n = i & 127;
        float v = W1[i];
        __nv_bfloat16 h = __float2bfloat16(v);
        g_b1hi[n * F + k] = h;
        g_b1lo[n * F + k] = __float2bfloat16(v - __bfloat162float(h));
    } else if (i < F * F + F * NOUT2) {
        int q = i - F * F;
        int k = q >> 5, n = q & 31;
        float v = W2[q];
        __nv_bfloat16 h = __float2bfloat16(v);
        g_b2hi[n * F + k] = h;
        g_b2lo[n * F + k] = __float2bfloat16(v - __bfloat162float(h));
    }
    if (i == 0) {
        int is64 = 1;
        #pragma unroll
        for (int k = 0; k < 32; ++k)
            if (e32[2 * k + 1] != 0) { is64 = 0; break; }
        g_is64 = is64;
    }
}

// ---------------- degree histogram -----------------------------------------
__global__ void deg_kernel(const void* __restrict__ edges) {
    int e = blockIdx.x * blockDim.x + threadIdx.x;
    if (e >= NE) return;
    int d;
    if (g_is64) d = (int)((const long long*)edges)[NE + e];
    else        d = ((const int*)edges)[NE + e];
    atomicAdd(&g_degi[d], 1);
}

// ---------------- single-kernel scan with decoupled lookback ---------------
__global__ void scanlb_kernel() {
    __shared__ int wred[8];
    __shared__ int wscn[8];
    __shared__ int base_sh;
    int b = blockIdx.x, t = threadIdx.x;
    int lane = t & 31, warp = t >> 5;
    int i = b * SCAN_BS + t;
    int v = (i < N_NODES) ? g_degi[i] : 0;

    int s = v;
    #pragma unroll
    for (int off = 1; off < 32; off <<= 1) {
        int u = __shfl_up_sync(0xffffffffu, s, off);
        if (lane >= off) s += u;
    }
    if (lane == 31) wred[warp] = s;
    __syncthreads();
    if (t < 8) {
        int ws = wred[t];
        #pragma unroll
        for (int off = 1; off < 8; off <<= 1) {
            int u = __shfl_up_sync(0xffu, ws, off);
            if ((int)t >= off) ws += u;
        }
        wscn[t] = ws;
        if (t == 7) atomicExch(&g_lb[b], LBFLAG | (unsigned)ws);
    }
    __syncthreads();

    int contrib = 0;
    if (t < b) {
        unsigned f;
        do { f = atomicAdd(&g_lb[t], 0u); } while (!(f & LBFLAG));
        contrib = (int)(f & ~LBFLAG);
    }
    #pragma unroll
    for (int off = 16; off > 0; off >>= 1)
        contrib += __shfl_down_sync(0xffffffffu, contrib, off);
    if (lane == 0) wred[warp] = contrib;
    __syncthreads();
    if (t == 0) {
        int base = 0;
        #pragma unroll
        for (int k = 0; k < 8; ++k) base += wred[k];
        base_sh = base;
        if (b == 0) g_rowptr[N_NODES] = NE;
    }
    __syncthreads();

    int excl = base_sh + (warp > 0 ? wscn[warp - 1] : 0) + (s - v);
    if (i < N_NODES) { g_rowptr[i] = excl; g_cur[i] = excl; }
}

// ---------------- CSR fill --------------------------------------------------
__global__ void fill_kernel(const void* __restrict__ edges) {
    int e = blockIdx.x * blockDim.x + threadIdx.x;
    if (e >= NE) return;
    int s, d;
    if (g_is64) {
        s = (int)((const long long*)edges)[e];
        d = (int)((const long long*)edges)[NE + e];
    } else {
        s = ((const int*)edges)[e];
        d = ((const int*)edges)[NE + e];
    }
    int pos = atomicAdd(&g_cur[d], 1);
    g_csr[pos] = s;
}

// ---------------- mma.sync GEMM: Yh = A @ B^T (fp16 out) -------------------
template<int NCOLS, int LAYER>
__global__ __launch_bounds__(256) void gemm_mma_kernel(const float* __restrict__ x) {
    constexpr int ROWS = 64;
    constexpr int SROW = 136;
    constexpr int A_BYTES = ROWS * SROW * 2;
    constexpr int B_BYTES = NCOLS * SROW * 2;
    constexpr int OF_AHI = 0;
    constexpr int OF_ALO = A_BYTES;
    constexpr int OF_BHI = 2 * A_BYTES;
    constexpr int OF_BLO = OF_BHI + B_BYTES;
    constexpr int N8  = NCOLS / 32;
    constexpr int WNT = NCOLS / 4;
    constexpr int CS  = NCOLS + 4;

    const __nv_bfloat16* Bhi = (LAYER == 1) ? g_b1hi : g_b2hi;
    const __nv_bfloat16* Blo = (LAYER == 1) ? g_b1lo : g_b2lo;
    __half* Yh = (LAYER == 1) ? g_y1h : g_y2h;

    extern __shared__ char smem[];
    float* Csm = (float*)smem;
    uint32_t sb = smem_u32(smem);

    int t = threadIdx.x, lane = t & 31, wid = t >> 5;
    int row0 = blockIdx.x * ROWS;

    if constexpr (LAYER == 1) {
        for (int i = t; i < ROWS * 32; i += 256) {
            int r = i >> 5, c4 = i & 31;
            int gr = row0 + r;
            float4 v = make_float4(0.f, 0.f, 0.f, 0.f);
            if (gr < N_NODES) v = ((const float4*)(x + (size_t)gr * F))[c4];
            __nv_bfloat162 h0 = __floats2bfloat162_rn(v.x, v.y);
            __nv_bfloat162 h1 = __floats2bfloat162_rn(v.z, v.w);
            __nv_bfloat162 l0 = __floats2bfloat162_rn(v.x - __low2float(h0),
                                                      v.y - __high2float(h0));
            __nv_bfloat162 l1 = __floats2bfloat162_rn(v.z - __low2float(h1),
                                                      v.w - __high2float(h1));
            uint2 uh, ul;
            uh.x = *reinterpret_cast<uint32_t*>(&h0);
            uh.y = *reinterpret_cast<uint32_t*>(&h1);
            ul.x = *reinterpret_cast<uint32_t*>(&l0);
            ul.y = *reinterpret_cast<uint32_t*>(&l1);
            *(uint2*)(smem + OF_AHI + r * (SROW * 2) + c4 * 8) = uh;
            *(uint2*)(smem + OF_ALO + r * (SROW * 2) + c4 * 8) = ul;
        }
    } else {
        for (int i = t; i < ROWS * 16; i += 256) {
            int r = i >> 4, c = (i & 15) * 8;
            int gr = row0 + r;
            uint4 vh = make_uint4(0, 0, 0, 0), vl = make_uint4(0, 0, 0, 0);
            if (gr < N_NODES) {
                vh = *(const uint4*)(g_h1hi + (size_t)gr * F + c);
                vl = *(const uint4*)(g_h1lo + (size_t)gr * F + c);
            }
            *(uint4*)(smem + OF_AHI + r * (SROW * 2) + c * 2) = vh;
            *(uint4*)(smem + OF_ALO + r * (SROW * 2) + c * 2) = vl;
        }
    }
    for (int i = t; i < NCOLS * 16; i += 256) {
        int r = i >> 4, c = (i & 15) * 8;
        *(uint4*)(smem + OF_BHI + r * (SROW * 2) + c * 2) =
            *(const uint4*)(Bhi + (size_t)r * F + c);
        *(uint4*)(smem + OF_BLO + r * (SROW * 2) + c * 2) =
            *(const uint4*)(Blo + (size_t)r * F + c);
    }
    __syncthreads();

    int wm = wid & 1, wn = wid >> 1;
    int m0 = wm * 32, n0 = wn * WNT;

    float acc[2][N8][4];
    #pragma unroll
    for (int mi = 0; mi < 2; ++mi)
        #pragma unroll
        for (int nj = 0; nj < N8; ++nj)
            #pragma unroll
            for (int q = 0; q < 4; ++q) acc[mi][nj][q] = 0.f;

    int lrow = lane & 7, lsub = lane >> 3;
    int aRow = lrow + (lsub & 1) * 8, aCol = (lsub >> 1) * 8;
    int bRow = lrow + (lsub >> 1) * 8, bCol = (lsub & 1) * 8;
    int l16 = lane & 15;
    int b2Row = l16 & 7, b2Col = (l16 >> 3) * 8;

    const int passA[3] = { OF_AHI, OF_AHI, OF_ALO };
    const int passB[3] = { OF_BHI, OF_BLO, OF_BHI };

    #pragma unroll
    for (int p = 0; p < 3; ++p) {
        uint32_t Ab = sb + passA[p], Bb = sb + passB[p];
        #pragma unroll
        for (int k = 0; k < 8; ++k) {
            int k0 = k * 16;
            uint32_t a[2][4];
            #pragma unroll
            for (int mi = 0; mi < 2; ++mi) {
                uint32_t ad = Ab + ((m0 + mi * 16 + aRow) * SROW + k0 + aCol) * 2;
                LDSM4(a[mi][0], a[mi][1], a[mi][2], a[mi][3], ad);
            }
            uint32_t b[N8][2];
            if constexpr (N8 == 1) {
                uint32_t bd = Bb + ((n0 + b2Row) * SROW + k0 + b2Col) * 2;
                LDSM2(b[0][0], b[0][1], bd);
            } else {
                #pragma unroll
                for (int nj2 = 0; nj2 < N8 / 2; ++nj2) {
                    uint32_t bd = Bb + ((n0 + nj2 * 16 + bRow) * SROW + k0 + bCol) * 2;
                    uint32_t r0, r1, r2, r3;
                    LDSM4(r0, r1, r2, r3, bd);
                    b[nj2 * 2][0] = r0; b[nj2 * 2][1] = r1;
                    b[nj2 * 2 + 1][0] = r2; b[nj2 * 2 + 1][1] = r3;
                }
            }
            #pragma unroll
            for (int mi = 0; mi < 2; ++mi)
                #pragma unroll
                for (int nj = 0; nj < N8; ++nj)
                    MMA16816(acc[mi][nj], a[mi], b[nj]);
        }
    }

    __syncthreads();

    int g = lane >> 2, tp = lane & 3;
    #pragma unroll
    for (int mi = 0; mi < 2; ++mi)
        #pragma unroll
        for (int nj = 0; nj < N8; ++nj) {
            int rr = m0 + mi * 16 + g;
            int cc = n0 + nj * 8 + tp * 2;
            Csm[rr * CS + cc]           = acc[mi][nj][0];
            Csm[rr * CS + cc + 1]       = acc[mi][nj][1];
            Csm[(rr + 8) * CS + cc]     = acc[mi][nj][2];
            Csm[(rr + 8) * CS + cc + 1] = acc[mi][nj][3];
        }
    __syncthreads();

    for (int i = t; i < ROWS * (NCOLS / 8); i += 256) {
        int r = i / (NCOLS / 8), c8 = (i % (NCOLS / 8)) * 8;
        int row = row0 + r;
        if (row < N_NODES) {
            float4 u = *(float4*)&Csm[r * CS + c8];
            float4 w = *(float4*)&Csm[r * CS + c8 + 4];
            __half2 p0 = __floats2half2_rn(u.x, u.y);
            __half2 p1 = __floats2half2_rn(u.z, u.w);
            __half2 p2 = __floats2half2_rn(w.x, w.y);
            __half2 p3 = __floats2half2_rn(w.z, w.w);
            uint4 o;
            o.x = *reinterpret_cast<uint32_t*>(&p0);
            o.y = *reinterpret_cast<uint32_t*>(&p1);
            o.z = *reinterpret_cast<uint32_t*>(&p2);
            o.w = *reinterpret_cast<uint32_t*>(&p3);
            *(uint4*)(Yh + (size_t)row * NCOLS + c8) = o;
        }
    }
}

// ---------------- agg1: h1 = leaky((sum_nbr y1 + y1)*rinv + b1) -> bf16 ----
// 8 blocks/SM (<=32 regs) for full occupancy; int4-aligned index loads.
__global__ __launch_bounds__(256, 8) void agg1_kernel(const float* __restrict__ b1g) {
    int w = (blockIdx.x * blockDim.x + threadIdx.x) >> 5;
    if (w >= N_NODES) return;
    int lane = threadIdx.x & 31;
    const uint2* Y = (const uint2*)g_y1h;

    float4 a0 = make_float4(0.f, 0.f, 0.f, 0.f);
    float4 a1 = a0;
    acc_h4(a0, Y[(size_t)w * 32 + lane]);   // self

    int beg = g_rowptr[w], end = g_rowptr[w + 1];
    int j = beg;
    // prologue: align j to 4
    for (; j < end && (j & 3); ++j)
        acc_h4(a1, Y[(size_t)g_csr[j] * 32 + lane]);
    for (; j + 4 <= end; j += 4) {
        int4 s4 = *(const int4*)&g_csr[j];
        uint2 u0 = Y[(size_t)s4.x * 32 + lane];
        uint2 u1 = Y[(size_t)s4.y * 32 + lane];
        uint2 u2 = Y[(size_t)s4.z * 32 + lane];
        uint2 u3 = Y[(size_t)s4.w * 32 + lane];
        acc_h4(a0, u0);
        acc_h4(a1, u1);
        acc_h4(a0, u2);
        acc_h4(a1, u3);
    }
    for (; j < end; ++j)
        acc_h4(a0, Y[(size_t)g_csr[j] * 32 + lane]);

    float rinv = 1.0f / (float)(end - beg + 1);
    float4 b = ((const float4*)b1g)[lane];
    float4 h;
    h.x = (a0.x + a1.x) * rinv + b.x;
    h.y = (a0.y + a1.y) * rinv + b.y;
    h.z = (a0.z + a1.z) * rinv + b.z;
    h.w = (a0.w + a1.w) * rinv + b.w;
    h.x = h.x >= 0.f ? h.x : 0.01f * h.x;
    h.y = h.y >= 0.f ? h.y : 0.01f * h.y;
    h.z = h.z >= 0.f ? h.z : 0.01f * h.z;
    h.w = h.w >= 0.f ? h.w : 0.01f * h.w;

    __nv_bfloat162 p0 = __floats2bfloat162_rn(h.x, h.y);
    __nv_bfloat162 p1 = __floats2bfloat162_rn(h.z, h.w);
    __nv_bfloat162 q0 = __floats2bfloat162_rn(h.x - __low2float(p0), h.y - __high2float(p0));
    __nv_bfloat162 q1 = __floats2bfloat162_rn(h.z - __low2float(p1), h.w - __high2float(p1));
    ((__nv_bfloat162*)g_h1hi)[(size_t)w * 64 + lane * 2]     = p0;
    ((__nv_bfloat162*)g_h1hi)[(size_t)w * 64 + lane * 2 + 1] = p1;
    ((__nv_bfloat162*)g_h1lo)[(size_t)w * 64 + lane * 2]     = q0;
    ((__nv_bfloat162*)g_h1lo)[(size_t)w * 64 + lane * 2 + 1] = q1;
}

// ---------------- agg2: out = (sum_nbr y2 + y2)*rinv + b2 ------------------
__global__ __launch_bounds__(256, 8) void agg2_kernel(const float* __restrict__ b2g,
                                                      float* __restrict__ out) {
    int gw = (blockIdx.x * blockDim.x + threadIdx.x) >> 5;
    int lane = threadIdx.x & 31;
    int node = gw * 4 + (lane >> 3);
    if (node >= N_NODES) return;
    int l8 = lane & 7;
    const uint2* Y = (const uint2*)g_y2h;

    float4 a0 = make_float4(0.f, 0.f, 0.f, 0.f);
    float4 a1 = a0;
    acc_h4(a0, Y[(size_t)node * 8 + l8]);   // self

    int beg = g_rowptr[node], end = g_rowptr[node + 1];
    int j = beg;
    for (; j < end && (j & 3); ++j)
        acc_h4(a1, Y[(size_t)g_csr[j] * 8 + l8]);
    for (; j + 4 <= end; j += 4) {
        int4 s4 = *(const int4*)&g_csr[j];
        uint2 u0 = Y[(size_t)s4.x * 8 + l8];
        uint2 u1 = Y[(size_t)s4.y * 8 + l8];
        uint2 u2 = Y[(size_t)s4.z * 8 + l8];
        uint2 u3 = Y[(size_t)s4.w * 8 + l8];
        acc_h4(a0, u0);
        acc_h4(a1, u1);
        acc_h4(a0, u2);
        acc_h4(a1, u3);
    }
    for (; j < end; ++j)
        acc_h4(a0, Y[(size_t)g_csr[j] * 8 + l8]);

    float rinv = 1.0f / (float)(end - beg + 1);
    float4 b = ((const float4*)b2g)[l8];
    float4 o;
    o.x = (a0.x + a1.x) * rinv + b.x;
    o.y = (a0.y + a1.y) * rinv + b.y;
    o.z = (a0.z + a1.z) * rinv + b.z;
    o.w = (a0.w + a1.w) * rinv + b.w;
    ((float4*)(out + (size_t)node * NOUT2))[l8] = o;
}

// ---------------- launch ----------------------------------------------------
extern "C" void kernel_launch(void* const* d_in, const int* in_sizes, int n_in,
                              void* d_out, int out_size) {
    const float* in_feat = (const float*)d_in[0];
    const void*  edges   = d_in[1];
    const float* W1      = (const float*)d_in[2];
    const float* b1      = (const float*)d_in[3];
    const float* W2      = (const float*)d_in[4];
    const float* b2      = (const float*)d_in[5];
    float* out = (float*)d_out;

    const int smem_g1 = 2 * (64 * 136 * 2) + 2 * (128 * 136 * 2);   // 104,448
    const int smem_g2 = 2 * (64 * 136 * 2) + 2 * (32 * 136 * 2);    //  52,224
    cudaFuncSetAttribute(gemm_mma_kernel<128, 1>,
                         cudaFuncAttributeMaxDynamicSharedMemorySize, smem_g1);
    cudaFuncSetAttribute(gemm_mma_kernel<32, 2>,
                         cudaFuncAttributeMaxDynamicSharedMemorySize, smem_g2);

    cudaStream_t s2;
    cudaEvent_t evFork, evJoin;
    cudaStreamCreateWithFlags(&s2, cudaStreamNonBlocking);
    cudaEventCreateWithFlags(&evFork, cudaEventDisableTiming);
    cudaEventCreateWithFlags(&evJoin, cudaEventDisableTiming);

    const int GB = (N_NODES + 63) / 64;   // 782

    // init feeds both chains (zeroes degi/lb, splits W, detects dtype)
    init_kernel<<<(N_NODES + 255) / 256, 256>>>((const int*)edges, W1, W2);
    cudaEventRecord(evFork, 0);

    // chain B (side stream): GEMM1 — independent of CSR build
    cudaStreamWaitEvent(s2, evFork, 0);
    gemm_mma_kernel<128, 1><<<GB, 256, smem_g1, s2>>>(in_feat);
    cudaEventRecord(evJoin, s2);

    // chain A (legacy stream): CSR build
    deg_kernel<<<(NE + 255) / 256, 256>>>(edges);
    scanlb_kernel<<<SCAN_NB, SCAN_BS>>>();
    fill_kernel<<<(NE + 255) / 256, 256>>>(edges);

    // join: agg1 needs CSR (legacy) + y1h (side)
    cudaStreamWaitEvent(0, evJoin, 0);
    agg1_kernel<<<(N_NODES * 32 + 255) / 256, 256>>>(b1);
    gemm_mma_kernel<32, 2><<<GB, 256, smem_g2>>>(nullptr);
    agg2_kernel<<<((N_NODES + 3) / 4 * 32 + 255) / 256, 256>>>(b2, out);
}

// round 16
// speedup vs baseline: 1.1224x; 1.0128x over previous
#include <cuda_runtime.h>
#include <cuda_bf16.h>
#include <cuda_fp16.h>
#include <cstdint>

#define N_NODES 50000
#define F 128
#define NOUT2 32
#define NE 800000

#define SCAN_BS 256
#define SCAN_NB ((N_NODES + SCAN_BS - 1) / SCAN_BS)   // 196
#define LBFLAG 0x80000000u

// ---------------- scratch (device globals: no allocation allowed) ----------
// INVARIANT: g_degi and g_lb are all-zero on entry to kernel_launch
// (zero-initialized at module load; agg2 re-zeros them every call).
__device__ __align__(16) __half g_y1h[N_NODES * F];      // x @ W1 (fp16)
__device__ __align__(16) __half g_y2h[N_NODES * NOUT2];  // h1 @ W2 (fp16)
__device__ __align__(16) __nv_bfloat16 g_h1hi[N_NODES * F];
__device__ __align__(16) __nv_bfloat16 g_h1lo[N_NODES * F];
__device__ __align__(16) __nv_bfloat16 g_b1hi[F * F];     // W1^T [n][k]
__device__ __align__(16) __nv_bfloat16 g_b1lo[F * F];
__device__ __align__(16) __nv_bfloat16 g_b2hi[NOUT2 * F]; // W2^T [n][k]
__device__ __align__(16) __nv_bfloat16 g_b2lo[NOUT2 * F];
__device__ __align__(16) int g_csr[NE];
__device__ int g_rowptr[N_NODES + 1];
__device__ int g_cur[N_NODES];
__device__ int g_degi[N_NODES];
__device__ unsigned g_lb[SCAN_NB];
__device__ int g_is64;

// ---------------- helpers ---------------------------------------------------
__device__ __forceinline__ uint32_t smem_u32(const void* p) {
    uint32_t a;
    asm("{ .reg .u64 t; cvta.to.shared.u64 t, %1; cvt.u32.u64 %0, t; }"
        : "=r"(a) : "l"(p));
    return a;
}
#define LDSM4(r0, r1, r2, r3, a) \
    asm volatile("ldmatrix.sync.aligned.m8n8.x4.shared.b16 {%0,%1,%2,%3}, [%4];" \
                 : "=r"(r0), "=r"(r1), "=r"(r2), "=r"(r3) : "r"(a))
#define LDSM2(r0, r1, a) \
    asm volatile("ldmatrix.sync.aligned.m8n8.x2.shared.b16 {%0,%1}, [%2];" \
                 : "=r"(r0), "=r"(r1) : "r"(a))
#define MMA16816(c, a, b) \
    asm volatile("mma.sync.aligned.m16n8k16.row.col.f32.bf16.bf16.f32 " \
                 "{%0,%1,%2,%3}, {%4,%5,%6,%7}, {%8,%9}, {%0,%1,%2,%3};" \
                 : "+f"((c)[0]), "+f"((c)[1]), "+f"((c)[2]), "+f"((c)[3]) \
                 : "r"((a)[0]), "r"((a)[1]), "r"((a)[2]), "r"((a)[3]), \
                   "r"((b)[0]), "r"((b)[1]))

__device__ __forceinline__ void acc_h4(float4& a, uint2 u) {
    float2 f0 = __half22float2(*reinterpret_cast<__half2*>(&u.x));
    float2 f1 = __half22float2(*reinterpret_cast<__half2*>(&u.y));
    a.x += f0.x; a.y += f0.y; a.z += f1.x; a.w += f1.y;
}

__device__ __forceinline__ int block_detect_is64(const int* e32) {
    int is64 = 1;
    #pragma unroll
    for (int k = 0; k < 32; ++k)
        if (e32[2 * k + 1] != 0) { is64 = 0; break; }
    return is64;
}

// ---------------- init: deg histogram + W hi/lo split + dtype publish ------
// (g_degi pre-zeroed by invariant; no zeroing pass needed)
__global__ void init_kernel(const void* __restrict__ edges,
                            const float* __restrict__ W1,
                            const float* __restrict__ W2) {
    __shared__ int s64;
    if (threadIdx.x == 0) s64 = block_detect_is64((const int*)edges);
    __syncthreads();

    int i = blockIdx.x * blockDim.x + threadIdx.x;
    if (i == 0) g_is64 = s64;                 // for fill_kernel
    if (i < F * F) {                          // W1 split/transpose
        int k = i >> 7, n = i & 127;
        float v = W1[i];
        __nv_bfloat16 h = __float2bfloat16(v);
        g_b1hi[n * F + k] = h;
        g_b1lo[n * F + k] = __float2bfloat16(v - __bfloat162float(h));
    } else if (i < F * F + F * NOUT2) {       // W2 split/transpose
        int q = i - F * F;
        int k = q >> 5, n = q & 31;
        float v = W2[q];
        __nv_bfloat16 h = __float2bfloat16(v);
        g_b2hi[n * F + k] = h;
        g_b2lo[n * F + k] = __float2bfloat16(v - __bfloat162float(h));
    }
    if (i >= NE) return;
    int d = s64 ? (int)((const long long*)edges)[NE + i]
                : ((const int*)edges)[NE + i];
    atomicAdd(&g_degi[d], 1);
}

// ---------------- single-kernel scan with decoupled lookback ---------------
__global__ void scanlb_kernel() {
    __shared__ int wred[8];
    __shared__ int wscn[8];
    __shared__ int base_sh;
    int b = blockIdx.x, t = threadIdx.x;
    int lane = t & 31, warp = t >> 5;
    int i = b * SCAN_BS + t;
    int v = (i < N_NODES) ? g_degi[i] : 0;

    int s = v;
    #pragma unroll
    for (int off = 1; off < 32; off <<= 1) {
        int u = __shfl_up_sync(0xffffffffu, s, off);
        if (lane >= off) s += u;
    }
    if (lane == 31) wred[warp] = s;
    __syncthreads();
    if (t < 8) {
        int ws = wred[t];
        #pragma unroll
        for (int off = 1; off < 8; off <<= 1) {
            int u = __shfl_up_sync(0xffu, ws, off);
            if ((int)t >= off) ws += u;
        }
        wscn[t] = ws;
        if (t == 7) atomicExch(&g_lb[b], LBFLAG | (unsigned)ws);
    }
    __syncthreads();

    int contrib = 0;
    if (t < b) {
        unsigned f;
        do { f = atomicAdd(&g_lb[t], 0u); } while (!(f & LBFLAG));
        contrib = (int)(f & ~LBFLAG);
    }
    #pragma unroll
    for (int off = 16; off > 0; off >>= 1)
        contrib += __shfl_down_sync(0xffffffffu, contrib, off);
    if (lane == 0) wred[warp] = contrib;
    __syncthreads();
    if (t == 0) {
        int base = 0;
        #pragma unroll
        for (int k = 0; k < 8; ++k) base += wred[k];
        base_sh = base;
        if (b == 0) g_rowptr[N_NODES] = NE;
    }
    __syncthreads();

    int excl = base_sh + (warp > 0 ? wscn[warp - 1] : 0) + (s - v);
    if (i < N_NODES) { g_rowptr[i] = excl; g_cur[i] = excl; }
}

// ---------------- CSR fill --------------------------------------------------
__global__ void fill_kernel(const void* __restrict__ edges) {
    int e = blockIdx.x * blockDim.x + threadIdx.x;
    if (e >= NE) return;
    int s, d;
    if (g_is64) {
        s = (int)((const long long*)edges)[e];
        d = (int)((const long long*)edges)[NE + e];
    } else {
        s = ((const int*)edges)[e];
        d = ((const int*)edges)[NE + e];
    }
    int pos = atomicAdd(&g_cur[d], 1);
    g_csr[pos] = s;
}

// ---------------- mma.sync GEMM: Yh = A @ B^T (fp16 out) -------------------
template<int NCOLS, int LAYER>
__global__ __launch_bounds__(256) void gemm_mma_kernel(const float* __restrict__ x) {
    constexpr int ROWS = 64;
    constexpr int SROW = 136;
    constexpr int A_BYTES = ROWS * SROW * 2;
    constexpr int B_BYTES = NCOLS * SROW * 2;
    constexpr int OF_AHI = 0;
    constexpr int OF_ALO = A_BYTES;
    constexpr int OF_BHI = 2 * A_BYTES;
    constexpr int OF_BLO = OF_BHI + B_BYTES;
    constexpr int N8  = NCOLS / 32;
    constexpr int WNT = NCOLS / 4;
    constexpr int CS  = NCOLS + 4;

    const __nv_bfloat16* Bhi = (LAYER == 1) ? g_b1hi : g_b2hi;
    const __nv_bfloat16* Blo = (LAYER == 1) ? g_b1lo : g_b2lo;
    __half* Yh = (LAYER == 1) ? g_y1h : g_y2h;

    extern __shared__ char smem[];
    float* Csm = (float*)smem;
    uint32_t sb = smem_u32(smem);

    int t = threadIdx.x, lane = t & 31, wid = t >> 5;
    int row0 = blockIdx.x * ROWS;

    if constexpr (LAYER == 1) {
        for (int i = t; i < ROWS * 32; i += 256) {
            int r = i >> 5, c4 = i & 31;
            int gr = row0 + r;
            float4 v = make_float4(0.f, 0.f, 0.f, 0.f);
            if (gr < N_NODES) v = ((const float4*)(x + (size_t)gr * F))[c4];
            __nv_bfloat162 h0 = __floats2bfloat162_rn(v.x, v.y);
            __nv_bfloat162 h1 = __floats2bfloat162_rn(v.z, v.w);
            __nv_bfloat162 l0 = __floats2bfloat162_rn(v.x - __low2float(h0),
                                                      v.y - __high2float(h0));
            __nv_bfloat162 l1 = __floats2bfloat162_rn(v.z - __low2float(h1),
                                                      v.w - __high2float(h1));
            uint2 uh, ul;
            uh.x = *reinterpret_cast<uint32_t*>(&h0);
            uh.y = *reinterpret_cast<uint32_t*>(&h1);
            ul.x = *reinterpret_cast<uint32_t*>(&l0);
            ul.y = *reinterpret_cast<uint32_t*>(&l1);
            *(uint2*)(smem + OF_AHI + r * (SROW * 2) + c4 * 8) = uh;
            *(uint2*)(smem + OF_ALO + r * (SROW * 2) + c4 * 8) = ul;
        }
    } else {
        for (int i = t; i < ROWS * 16; i += 256) {
            int r = i >> 4, c = (i & 15) * 8;
            int gr = row0 + r;
            uint4 vh = make_uint4(0, 0, 0, 0), vl = make_uint4(0, 0, 0, 0);
            if (gr < N_NODES) {
                vh = *(const uint4*)(g_h1hi + (size_t)gr * F + c);
                vl = *(const uint4*)(g_h1lo + (size_t)gr * F + c);
            }
            *(uint4*)(smem + OF_AHI + r * (SROW * 2) + c * 2) = vh;
            *(uint4*)(smem + OF_ALO + r * (SROW * 2) + c * 2) = vl;
        }
    }
    for (int i = t; i < NCOLS * 16; i += 256) {
        int r = i >> 4, c = (i & 15) * 8;
        *(uint4*)(smem + OF_BHI + r * (SROW * 2) + c * 2) =
            *(const uint4*)(Bhi + (size_t)r * F + c);
        *(uint4*)(smem + OF_BLO + r * (SROW * 2) + c * 2) =
            *(const uint4*)(Blo + (size_t)r * F + c);
    }
    __syncthreads();

    int wm = wid & 1, wn = wid >> 1;
    int m0 = wm * 32, n0 = wn * WNT;

    float acc[2][N8][4];
    #pragma unroll
    for (int mi = 0; mi < 2; ++mi)
        #pragma unroll
        for (int nj = 0; nj < N8; ++nj)
            #pragma unroll
            for (int q = 0; q < 4; ++q) acc[mi][nj][q] = 0.f;

    int lrow = lane & 7, lsub = lane >> 3;
    int aRow = lrow + (lsub & 1) * 8, aCol = (lsub >> 1) * 8;
    int bRow = lrow + (lsub >> 1) * 8, bCol = (lsub & 1) * 8;
    int l16 = lane & 15;
    int b2Row = l16 & 7, b2Col = (l16 >> 3) * 8;

    const int passA[3] = { OF_AHI, OF_AHI, OF_ALO };
    const int passB[3] = { OF_BHI, OF_BLO, OF_BHI };

    #pragma unroll
    for (int p = 0; p < 3; ++p) {
        uint32_t Ab = sb + passA[p], Bb = sb + passB[p];
        #pragma unroll
        for (int k = 0; k < 8; ++k) {
            int k0 = k * 16;
            uint32_t a[2][4];
            #pragma unroll
            for (int mi = 0; mi < 2; ++mi) {
                uint32_t ad = Ab + ((m0 + mi * 16 + aRow) * SROW + k0 + aCol) * 2;
                LDSM4(a[mi][0], a[mi][1], a[mi][2], a[mi][3], ad);
            }
            uint32_t b[N8][2];
            if constexpr (N8 == 1) {
                uint32_t bd = Bb + ((n0 + b2Row) * SROW + k0 + b2Col) * 2;
                LDSM2(b[0][0], b[0][1], bd);
            } else {
                #pragma unroll
                for (int nj2 = 0; nj2 < N8 / 2; ++nj2) {
                    uint32_t bd = Bb + ((n0 + nj2 * 16 + bRow) * SROW + k0 + bCol) * 2;
                    uint32_t r0, r1, r2, r3;
                    LDSM4(r0, r1, r2, r3, bd);
                    b[nj2 * 2][0] = r0; b[nj2 * 2][1] = r1;
                    b[nj2 * 2 + 1][0] = r2; b[nj2 * 2 + 1][1] = r3;
                }
            }
            #pragma unroll
            for (int mi = 0; mi < 2; ++mi)
                #pragma unroll
                for (int nj = 0; nj < N8; ++nj)
                    MMA16816(acc[mi][nj], a[mi], b[nj]);
        }
    }

    __syncthreads();

    int g = lane >> 2, tp = lane & 3;
    #pragma unroll
    for (int mi = 0; mi < 2; ++mi)
        #pragma unroll
        for (int nj = 0; nj < N8; ++nj) {
            int rr = m0 + mi * 16 + g;
            int cc = n0 + nj * 8 + tp * 2;
            Csm[rr * CS + cc]           = acc[mi][nj][0];
            Csm[rr * CS + cc + 1]       = acc[mi][nj][1];
            Csm[(rr + 8) * CS + cc]     = acc[mi][nj][2];
            Csm[(rr + 8) * CS + cc + 1] = acc[mi][nj][3];
        }
    __syncthreads();

    for (int i = t; i < ROWS * (NCOLS / 8); i += 256) {
        int r = i / (NCOLS / 8), c8 = (i % (NCOLS / 8)) * 8;
        int row = row0 + r;
        if (row < N_NODES) {
            float4 u = *(float4*)&Csm[r * CS + c8];
            float4 w = *(float4*)&Csm[r * CS + c8 + 4];
            __half2 p0 = __floats2half2_rn(u.x, u.y);
            __half2 p1 = __floats2half2_rn(u.z, u.w);
            __half2 p2 = __floats2half2_rn(w.x, w.y);
            __half2 p3 = __floats2half2_rn(w.z, w.w);
            uint4 o;
            o.x = *reinterpret_cast<uint32_t*>(&p0);
            o.y = *reinterpret_cast<uint32_t*>(&p1);
            o.z = *reinterpret_cast<uint32_t*>(&p2);
            o.w = *reinterpret_cast<uint32_t*>(&p3);
            *(uint4*)(Yh + (size_t)row * NCOLS + c8) = o;
        }
    }
}

// ---------------- agg1: h1 = leaky((sum_nbr y1 + y1)*rinv + b1) -> bf16 ----
__global__ __launch_bounds__(256, 8) void agg1_kernel(const float* __restrict__ b1g) {
    int w = (blockIdx.x * blockDim.x + threadIdx.x) >> 5;
    if (w >= N_NODES) return;
    int lane = threadIdx.x & 31;
    const uint2* Y = (const uint2*)g_y1h;

    float4 a0 = make_float4(0.f, 0.f, 0.f, 0.f);
    float4 a1 = a0;
    acc_h4(a0, Y[(size_t)w * 32 + lane]);   // self

    int beg = g_rowptr[w], end = g_rowptr[w + 1];
    int j = beg;
    for (; j < end && (j & 3); ++j)
        acc_h4(a1, Y[(size_t)g_csr[j] * 32 + lane]);
    for (; j + 4 <= end; j += 4) {
        int4 s4 = *(const int4*)&g_csr[j];
        uint2 u0 = Y[(size_t)s4.x * 32 + lane];
        uint2 u1 = Y[(size_t)s4.y * 32 + lane];
        uint2 u2 = Y[(size_t)s4.z * 32 + lane];
        uint2 u3 = Y[(size_t)s4.w * 32 + lane];
        acc_h4(a0, u0);
        acc_h4(a1, u1);
        acc_h4(a0, u2);
        acc_h4(a1, u3);
    }
    for (; j < end; ++j)
        acc_h4(a0, Y[(size_t)g_csr[j] * 32 + lane]);

    float rinv = 1.0f / (float)(end - beg + 1);
    float4 b = ((const float4*)b1g)[lane];
    float4 h;
    h.x = (a0.x + a1.x) * rinv + b.x;
    h.y = (a0.y + a1.y) * rinv + b.y;
    h.z = (a0.z + a1.z) * rinv + b.z;
    h.w = (a0.w + a1.w) * rinv + b.w;
    h.x = h.x >= 0.f ? h.x : 0.01f * h.x;
    h.y = h.y >= 0.f ? h.y : 0.01f * h.y;
    h.z = h.z >= 0.f ? h.z : 0.01f * h.z;
    h.w = h.w >= 0.f ? h.w : 0.01f * h.w;

    __nv_bfloat162 p0 = __floats2bfloat162_rn(h.x, h.y);
    __nv_bfloat162 p1 = __floats2bfloat162_rn(h.z, h.w);
    __nv_bfloat162 q0 = __floats2bfloat162_rn(h.x - __low2float(p0), h.y - __high2float(p0));
    __nv_bfloat162 q1 = __floats2bfloat162_rn(h.z - __low2float(p1), h.w - __high2float(p1));
    ((__nv_bfloat162*)g_h1hi)[(size_t)w * 64 + lane * 2]     = p0;
    ((__nv_bfloat162*)g_h1hi)[(size_t)w * 64 + lane * 2 + 1] = p1;
    ((__nv_bfloat162*)g_h1lo)[(size_t)w * 64 + lane * 2]     = q0;
    ((__nv_bfloat162*)g_h1lo)[(size_t)w * 64 + lane * 2 + 1] = q1;
}

// ---------------- agg2: out = (sum_nbr y2 + y2)*rinv + b2; reset scratch ---
__global__ __launch_bounds__(256, 8) void agg2_kernel(const float* __restrict__ b2g,
                                                      float* __restrict__ out) {
    int gi = blockIdx.x * blockDim.x + threadIdx.x;
    // restore the zero-invariant for the next call/replay
    if (gi < N_NODES) g_degi[gi] = 0;
    if (gi < SCAN_NB) g_lb[gi] = 0u;

    int gw = gi >> 5;
    int lane = threadIdx.x & 31;
    int node = gw * 4 + (lane >> 3);
    if (node >= N_NODES) return;
    int l8 = lane & 7;
    const uint2* Y = (const uint2*)g_y2h;

    float4 a0 = make_float4(0.f, 0.f, 0.f, 0.f);
    float4 a1 = a0;
    acc_h4(a0, Y[(size_t)node * 8 + l8]);   // self

    int beg = g_rowptr[node], end = g_rowptr[node + 1];
    int j = beg;
    for (; j < end && (j & 3); ++j)
        acc_h4(a1, Y[(size_t)g_csr[j] * 8 + l8]);
    for (; j + 4 <= end; j += 4) {
        int4 s4 = *(const int4*)&g_csr[j];
        uint2 u0 = Y[(size_t)s4.x * 8 + l8];
        uint2 u1 = Y[(size_t)s4.y * 8 + l8];
        uint2 u2 = Y[(size_t)s4.z * 8 + l8];
        uint2 u3 = Y[(size_t)s4.w * 8 + l8];
        acc_h4(a0, u0);
        acc_h4(a1, u1);
        acc_h4(a0, u2);
        acc_h4(a1, u3);
    }
    for (; j < end; ++j)
        acc_h4(a0, Y[(size_t)g_csr[j] * 8 + l8]);

    float rinv = 1.0f / (float)(end - beg + 1);
    float4 b = ((const float4*)b2g)[l8];
    float4 o;
    o.x = (a0.x + a1.x) * rinv + b.x;
    o.y = (a0.y + a1.y) * rinv + b.y;
    o.z = (a0.z + a1.z) * rinv + b.z;
    o.w = (a0.w + a1.w) * rinv + b.w;
    ((float4*)(out + (size_t)node * NOUT2))[l8] = o;
}

// ---------------- launch ----------------------------------------------------
extern "C" void kernel_launch(void* const* d_in, const int* in_sizes, int n_in,
                              void* d_out, int out_size) {
    const float* in_feat = (const float*)d_in[0];
    const void*  edges   = d_in[1];
    const float* W1      = (const float*)d_in[2];
    const float* b1      = (const float*)d_in[3];
    const float* W2      = (const float*)d_in[4];
    const float* b2      = (const float*)d_in[5];
    float* out = (float*)d_out;

    const int smem_g1 = 2 * (64 * 136 * 2) + 2 * (128 * 136 * 2);   // 104,448
    const int smem_g2 = 2 * (64 * 136 * 2) + 2 * (32 * 136 * 2);    //  52,224
    cudaFuncSetAttribute(gemm_mma_kernel<128, 1>,
                         cudaFuncAttributeMaxDynamicSharedMemorySize, smem_g1);
    cudaFuncSetAttribute(gemm_mma_kernel<32, 2>,
                         cudaFuncAttributeMaxDynamicSharedMemorySize, smem_g2);

    cudaStream_t s2;
    cudaEvent_t evFork, evJoin;
    cudaStreamCreateWithFlags(&s2, cudaStreamNonBlocking);
    cudaEventCreateWithFlags(&evFork, cudaEventDisableTiming);
    cudaEventCreateWithFlags(&evJoin, cudaEventDisableTiming);

    const int GB = (N_NODES + 63) / 64;   // 782

    // init: deg histogram + W split + dtype publish (one kernel, both chains)
    init_kernel<<<(NE + 255) / 256, 256>>>(edges, W1, W2);
    cudaEventRecord(evFork, 0);

    // chain B (side stream): GEMM1 — needs only W split
    cudaStreamWaitEvent(s2, evFork, 0);
    gemm_mma_kernel<128, 1><<<GB, 256, smem_g1, s2>>>(in_feat);
    cudaEventRecord(evJoin, s2);

    // chain A (legacy stream): scan + fill
    scanlb_kernel<<<SCAN_NB, SCAN_BS>>>();
    fill_kernel<<<(NE + 255) / 256, 256>>>(edges);

    // join: agg1 needs CSR (legacy) + y1h (side)
    cudaStreamWaitEvent(0, evJoin, 0);
    agg1_kernel<<<(N_NODES * 32 + 255) / 256, 256>>>(b1);
    gemm_mma_kernel<32, 2><<<GB, 256, smem_g2>>>(nullptr);
    agg2_kernel<<<((N_NODES + 3) / 4 * 32 + 255) / 256, 256>>>(b2, out);
}